// round 3
// baseline (speedup 1.0000x reference)
#include <cuda_runtime.h>
#include <math.h>

#define S 1024
#define U 128
#define D 64
#define EPS 1e-7f
#define MARGIN 0.5f

typedef unsigned long long ull;

// Scratch (device globals — no allocation allowed)
__device__ float g_centT[D * S];   // transposed normalized centroids [d][s]
__device__ float g_sel[S * D];     // hardest utterance per speaker
__device__ float g_intra[S];       // intra_d per speaker

// ---------------------------------------------------------------------------
// Kernel 1: centroid (register-accumulated during load) + normalize (deferred)
//           + intra argmin-of-clipped-cos + select hardest utterance
// grid = S blocks, 128 threads (thread u <-> utterance u)
// ---------------------------------------------------------------------------
__global__ __launch_bounds__(128) void k_centroid_intra(const float* __restrict__ x,
                                                        float* __restrict__ out) {
    const int s = blockIdx.x;
    const int t = threadIdx.x;

    __shared__ float4 sx4[U * 16];      // XOR-swizzled rows: 32 KB
    __shared__ float4 partials[128];
    __shared__ float  cent[D];          // raw mean centroid (unnormalized)
    __shared__ float  s_inv;
    __shared__ float  wval[4];
    __shared__ int    widx[4];
    __shared__ int    s_best;

    if (s == 0 && t == 0) out[0] = 0.0f;   // K2 runs strictly after K1

    // Load 32 KB tile; thread t's 16 float4 loads all belong to dim group
    // j = t&15 (since 128 % 16 == 0), so centroid partials accumulate in regs.
    const float4* xg = (const float4*)(x + (size_t)s * (U * D));
    const int jl = t & 15;
    float4 acc = make_float4(0.f, 0.f, 0.f, 0.f);
    #pragma unroll
    for (int k = 0; k < 16; k++) {
        int i = t + 128 * k;
        float4 v = xg[i];
        int u = i >> 4;
        sx4[u * 16 + ((jl + u) & 15)] = v;    // XOR swizzle: conflict-free both ways
        acc.x += v.x; acc.y += v.y; acc.z += v.z; acc.w += v.w;
    }
    partials[t] = acc;
    __syncthreads();

    // Reduce 8 partials per dim-group (threads 0..15), then norm (warp 0)
    if (t < 32) {
        float ss = 0.f;
        if (t < 16) {
            float4 c4 = make_float4(0.f, 0.f, 0.f, 0.f);
            #pragma unroll
            for (int h = 0; h < 8; h++) {
                float4 p = partials[h * 16 + t];
                c4.x += p.x; c4.y += p.y; c4.z += p.z; c4.w += p.w;
            }
            const float invU = 1.0f / (float)U;
            c4.x *= invU; c4.y *= invU; c4.z *= invU; c4.w *= invU;
            ((float4*)cent)[t] = c4;
            ss = c4.x * c4.x + c4.y * c4.y + c4.z * c4.z + c4.w * c4.w;
        }
        #pragma unroll
        for (int o = 16; o; o >>= 1) ss += __shfl_down_sync(0xffffffffu, ss, o);
        if (t == 0) s_inv = 1.0f / fmaxf(sqrtf(ss), 1e-12f);
    }
    __syncthreads();

    // Dot of utterance t with raw centroid, normalize once at the end
    const float inv = s_inv;
    float dot = 0.f;
    #pragma unroll
    for (int j = 0; j < 16; j++) {
        float4 v  = sx4[t * 16 + ((j + t) & 15)];
        float4 c4 = ((const float4*)cent)[j];
        dot = fmaf(v.x, c4.x, dot); dot = fmaf(v.y, c4.y, dot);
        dot = fmaf(v.z, c4.z, dot); dot = fmaf(v.w, c4.w, dot);
    }
    float cv = fminf(fmaxf(dot * inv, -1.0f + EPS), 1.0f - EPS);
    int   idx = t;

    // Warp argmin with first-index tie-break (on clipped value — faithful)
    #pragma unroll
    for (int o = 16; o; o >>= 1) {
        float ov = __shfl_down_sync(0xffffffffu, cv, o);
        int   oi = __shfl_down_sync(0xffffffffu, idx, o);
        if (ov < cv || (ov == cv && oi < idx)) { cv = ov; idx = oi; }
    }
    if ((t & 31) == 0) { wval[t >> 5] = cv; widx[t >> 5] = idx; }
    __syncthreads();

    if (t == 0) {
        float bv = wval[0]; int bi = widx[0];
        #pragma unroll
        for (int k = 1; k < 4; k++) {
            if (wval[k] < bv || (wval[k] == bv && widx[k] < bi)) { bv = wval[k]; bi = widx[k]; }
        }
        g_intra[s] = acosf(bv);
        s_best = bi;
    }
    __syncthreads();

    if (t < D) {
        int bi = s_best;
        const float* sxf = (const float*)sx4;
        int fj = t >> 2;
        g_sel[s * D + t]   = sxf[bi * 64 + ((fj + bi) & 15) * 4 + (t & 3)];
        g_centT[t * S + s] = cent[t] * inv;     // transposed, normalized
    }
}

// ---------------------------------------------------------------------------
// Kernel 2: dots = sel @ centroids^T via packed fma.rn.f32x2 (FFMA2),
//           then gather-max over tiled index pattern + hinge + atomic sum.
// grid = 128 blocks (8 speaker rows each), 256 threads.
// Thread t owns float2 column pairs p = t and t+256 -> columns {2t,2t+1},
// {512+2t, 513+2t}: packed operands come straight from LDG.64, no movs.
// ---------------------------------------------------------------------------
__global__ __launch_bounds__(256) void k_inter_loss(float* __restrict__ out) {
    const int j0 = blockIdx.x * 8;
    const int t  = threadIdx.x;

    __shared__ float sdots[8][S];     // 32 KB
    __shared__ ull   sseld[8][D];     // sel values pre-duplicated (lo|hi), 4 KB

    for (int i = t; i < 8 * D; i += 256) {
        unsigned int b = __float_as_uint(g_sel[(j0 + (i >> 6)) * D + (i & 63)]);
        sseld[i >> 6][i & 63] = ((ull)b << 32) | b;
    }
    __syncthreads();

    ull accA[8], accB[8];
    #pragma unroll
    for (int r = 0; r < 8; r++) { accA[r] = 0ull; accB[r] = 0ull; }  // (0.f,0.f)

    #pragma unroll 4
    for (int d = 0; d < D; d++) {
        const ull* ct2 = (const ull*)(g_centT + d * S);
        ull cA = ct2[t];
        ull cB = ct2[t + 256];
        #pragma unroll
        for (int r = 0; r < 8; r++) {
            ull sv2 = sseld[r][d];     // LDS.64 broadcast
            asm("fma.rn.f32x2 %0, %1, %2, %0;" : "+l"(accA[r]) : "l"(sv2), "l"(cA));
            asm("fma.rn.f32x2 %0, %1, %2, %0;" : "+l"(accB[r]) : "l"(sv2), "l"(cB));
        }
    }
    #pragma unroll
    for (int r = 0; r < 8; r++) {
        ((ull*)&sdots[r][0])[t]       = accA[r];   // cols 2t,2t+1
        ((ull*)&sdots[r][0])[t + 256] = accB[r];   // cols 512+2t,513+2t
    }
    __syncthreads();

    // Gather-max: warp w handles row j0+w. For flat m = j*1023+q the reference
    // tiling selects centroid c = ((m>>10) + 1 + (m & 1023)) & 1023.
    const int w = t >> 5, lane = t & 31;
    const int j = j0 + w;
    float mx = -3.4e38f;
    for (int q = lane; q < S - 1; q += 32) {
        int m = j * (S - 1) + q;
        int c = ((m >> 10) + 1 + (m & (S - 1))) & (S - 1);
        mx = fmaxf(mx, sdots[w][c]);
    }
    #pragma unroll
    for (int o = 16; o; o >>= 1) mx = fmaxf(mx, __shfl_down_sync(0xffffffffu, mx, o));

    if (lane == 0) {
        float md = fminf(fmaxf(mx, -1.0f + EPS), 1.0f - EPS);
        float term = fmaxf(MARGIN + g_intra[j] - acosf(md), 0.0f);
        atomicAdd(out, term);
    }
}

extern "C" void kernel_launch(void* const* d_in, const int* in_sizes, int n_in,
                              void* d_out, int out_size) {
    const float* x = (const float*)d_in[0];
    float* out = (float*)d_out;

    k_centroid_intra<<<S, 128>>>(x, out);
    k_inter_loss<<<S / 8, 256>>>(out);
}

// round 5
// speedup vs baseline: 1.4268x; 1.4268x over previous
#include <cuda_runtime.h>
#include <math.h>

#define S 1024
#define U 128
#define D 64
#define EPS 1e-7f
#define MARGIN 0.5f

typedef unsigned long long ull;

// Scratch (device globals — no allocation allowed)
__device__ float g_centT[D * S];            // transposed normalized centroids [d][s]
__device__ float g_selT[D * S];             // transposed hardest utterances [d][s]
__device__ float g_intra[S];                // intra_d per speaker
__device__ unsigned int g_rowmax[S];        // order-encoded max dot per row
__device__ unsigned int g_counter = 0;      // K2 completion counter

__device__ __forceinline__ unsigned int enc_f(float f) {
    unsigned int u = __float_as_uint(f);
    return (u & 0x80000000u) ? ~u : (u | 0x80000000u);
}
__device__ __forceinline__ float dec_f(unsigned int u) {
    unsigned int b = (u & 0x80000000u) ? (u ^ 0x80000000u) : ~u;
    return __uint_as_float(b);
}

// ---------------------------------------------------------------------------
// Kernel 1: centroid (register-accumulated during load) + normalize (deferred)
//           + intra argmin-of-clipped-cos + select hardest utterance.
// grid = S blocks, 128 threads (thread u <-> utterance u)
// ---------------------------------------------------------------------------
__global__ __launch_bounds__(128) void k_centroid_intra(const float* __restrict__ x) {
    const int s = blockIdx.x;
    const int t = threadIdx.x;

    __shared__ float4 sx4[U * 16];      // XOR-swizzled rows: 32 KB
    __shared__ float4 partials[128];
    __shared__ float  cent[D];
    __shared__ float  s_inv;
    __shared__ float  wval[4];
    __shared__ int    widx[4];
    __shared__ int    s_best;

    if (t == 0) {
        g_rowmax[s] = 0x00800000u;       // enc(-FLT_MAX); K2 runs after K1
        if (s == 0) g_counter = 0;       // recovery reset (stream-ordered before K2)
    }

    // Thread t's 16 float4 loads all hit dim group t&15 -> centroid in regs
    const float4* xg = (const float4*)(x + (size_t)s * (U * D));
    const int jl = t & 15;
    float4 acc = make_float4(0.f, 0.f, 0.f, 0.f);
    #pragma unroll
    for (int k = 0; k < 16; k++) {
        int i = t + 128 * k;
        float4 v = xg[i];
        int u = i >> 4;
        sx4[u * 16 + ((jl + u) & 15)] = v;    // XOR swizzle: conflict-free both ways
        acc.x += v.x; acc.y += v.y; acc.z += v.z; acc.w += v.w;
    }
    partials[t] = acc;
    __syncthreads();

    if (t < 32) {
        float ss = 0.f;
        if (t < 16) {
            float4 c4 = make_float4(0.f, 0.f, 0.f, 0.f);
            #pragma unroll
            for (int h = 0; h < 8; h++) {
                float4 p = partials[h * 16 + t];
                c4.x += p.x; c4.y += p.y; c4.z += p.z; c4.w += p.w;
            }
            const float invU = 1.0f / (float)U;
            c4.x *= invU; c4.y *= invU; c4.z *= invU; c4.w *= invU;
            ((float4*)cent)[t] = c4;
            ss = c4.x * c4.x + c4.y * c4.y + c4.z * c4.z + c4.w * c4.w;
        }
        #pragma unroll
        for (int o = 16; o; o >>= 1) ss += __shfl_down_sync(0xffffffffu, ss, o);
        if (t == 0) s_inv = 1.0f / fmaxf(sqrtf(ss), 1e-12f);
    }
    __syncthreads();

    const float inv = s_inv;
    float dot = 0.f;
    #pragma unroll
    for (int j = 0; j < 16; j++) {
        float4 v  = sx4[t * 16 + ((j + t) & 15)];
        float4 c4 = ((const float4*)cent)[j];
        dot = fmaf(v.x, c4.x, dot); dot = fmaf(v.y, c4.y, dot);
        dot = fmaf(v.z, c4.z, dot); dot = fmaf(v.w, c4.w, dot);
    }
    float cv = fminf(fmaxf(dot * inv, -1.0f + EPS), 1.0f - EPS);
    int   idx = t;

    // Warp argmin with first-index tie-break (on clipped value — faithful)
    #pragma unroll
    for (int o = 16; o; o >>= 1) {
        float ov = __shfl_down_sync(0xffffffffu, cv, o);
        int   oi = __shfl_down_sync(0xffffffffu, idx, o);
        if (ov < cv || (ov == cv && oi < idx)) { cv = ov; idx = oi; }
    }
    if ((t & 31) == 0) { wval[t >> 5] = cv; widx[t >> 5] = idx; }
    __syncthreads();

    if (t == 0) {
        float bv = wval[0]; int bi = widx[0];
        #pragma unroll
        for (int k = 1; k < 4; k++) {
            if (wval[k] < bv || (wval[k] == bv && widx[k] < bi)) { bv = wval[k]; bi = widx[k]; }
        }
        g_intra[s] = acosf(bv);
        s_best = bi;
    }
    __syncthreads();

    if (t < D) {
        int bi = s_best;
        const float* sxf = (const float*)sx4;
        int fj = t >> 2;
        g_selT[t * S + s]  = sxf[bi * 64 + ((fj + bi) & 15) * 4 + (t & 3)];
        g_centT[t * S + s] = cent[t] * inv;     // transposed, normalized
    }
}

// ---------------------------------------------------------------------------
// Kernel 2: tiled max-GEMM. inter max for row j = max_{c != j} sel_j . cent_c
// (the reference tiling's gather pattern excludes exactly c == j: for flat
// m = 1023j + q, c = ((m>>10)+1+(m&1023)) & 1023 walks all columns except j).
// grid = (8, 32): 32x128 tile per block, 256 threads, 4x4 micro-tile/thread,
// packed fma.rn.f32x2. Per-row atomicMax, last block does hinge+sum -> out.
// ---------------------------------------------------------------------------
__global__ __launch_bounds__(256) void k_inter(float* __restrict__ out) {
    __shared__ __align__(16) ull   sseld[D * 32];    // [k][r] sel dup'd, 16 KB
    __shared__ __align__(16) float scent[D * 128];   // [k][c], 32 KB
    __shared__ float swsum[8];
    __shared__ bool  is_last;

    const int t  = threadIdx.x;
    const int c0 = blockIdx.x * 128;
    const int j0 = blockIdx.y * 32;

    // Stage tiles (coalesced: rows of g_selT/g_centT are contiguous in s)
    for (int i = t; i < D * 32; i += 256) {
        int k = i >> 5, r = i & 31;
        unsigned int b = __float_as_uint(g_selT[k * S + j0 + r]);
        sseld[i] = ((ull)b << 32) | b;
    }
    for (int i = t; i < D * 32; i += 256) {          // 2048 float4
        int k = i >> 5, c4 = i & 31;
        ((float4*)scent)[i] = *(const float4*)(g_centT + k * S + c0 + c4 * 4);
    }
    __syncthreads();

    const int rg = t >> 5;     // warp id == row group (4 rows)
    const int cg = t & 31;     // col group (4 cols)

    ull acc[4][2];
    #pragma unroll
    for (int i = 0; i < 4; i++) { acc[i][0] = 0ull; acc[i][1] = 0ull; }

    #pragma unroll
    for (int k = 0; k < D; k++) {
        const ulonglong2* ap = (const ulonglong2*)(sseld + k * 32 + rg * 4);
        ulonglong2 a01 = ap[0];                      // LDS.128 broadcast
        ulonglong2 a23 = ap[1];
        ulonglong2 b   = ((const ulonglong2*)(scent + k * 128))[cg];  // LDS.128
        asm("fma.rn.f32x2 %0, %1, %2, %0;" : "+l"(acc[0][0]) : "l"(a01.x), "l"(b.x));
        asm("fma.rn.f32x2 %0, %1, %2, %0;" : "+l"(acc[0][1]) : "l"(a01.x), "l"(b.y));
        asm("fma.rn.f32x2 %0, %1, %2, %0;" : "+l"(acc[1][0]) : "l"(a01.y), "l"(b.x));
        asm("fma.rn.f32x2 %0, %1, %2, %0;" : "+l"(acc[1][1]) : "l"(a01.y), "l"(b.y));
        asm("fma.rn.f32x2 %0, %1, %2, %0;" : "+l"(acc[2][0]) : "l"(a23.x), "l"(b.x));
        asm("fma.rn.f32x2 %0, %1, %2, %0;" : "+l"(acc[2][1]) : "l"(a23.x), "l"(b.y));
        asm("fma.rn.f32x2 %0, %1, %2, %0;" : "+l"(acc[3][0]) : "l"(a23.y), "l"(b.x));
        asm("fma.rn.f32x2 %0, %1, %2, %0;" : "+l"(acc[3][1]) : "l"(a23.y), "l"(b.y));
    }

    // Per-row max over this thread's 4 cols (excluding c == j), then warp max
    #pragma unroll
    for (int i = 0; i < 4; i++) {
        const int j = j0 + rg * 4 + i;
        const int cb = c0 + cg * 4;
        float v0 = __uint_as_float((unsigned int)(acc[i][0] & 0xFFFFFFFFu));
        float v1 = __uint_as_float((unsigned int)(acc[i][0] >> 32));
        float v2 = __uint_as_float((unsigned int)(acc[i][1] & 0xFFFFFFFFu));
        float v3 = __uint_as_float((unsigned int)(acc[i][1] >> 32));
        float m = -3.4e38f;
        if (cb + 0 != j) m = fmaxf(m, v0);
        if (cb + 1 != j) m = fmaxf(m, v1);
        if (cb + 2 != j) m = fmaxf(m, v2);
        if (cb + 3 != j) m = fmaxf(m, v3);
        #pragma unroll
        for (int o = 16; o; o >>= 1) m = fmaxf(m, __shfl_xor_sync(0xffffffffu, m, o));
        if (cg == 0) atomicMax(&g_rowmax[j], enc_f(m));
    }

    // Last-block-done ticket (non-blocking): finisher does hinge+sum -> out
    __threadfence();
    if (t == 0) {
        unsigned int old = atomicAdd(&g_counter, 1);
        is_last = (old == gridDim.x * gridDim.y - 1);
    }
    __syncthreads();
    if (!is_last) return;

    float sum = 0.f;
    for (int j = t; j < S; j += 256) {
        unsigned int u = __ldcg(&g_rowmax[j]);   // L2-fresh (atomics live in L2)
        float md = fminf(fmaxf(dec_f(u), -1.0f + EPS), 1.0f - EPS);
        sum += fmaxf(MARGIN + g_intra[j] - acosf(md), 0.0f);
    }
    #pragma unroll
    for (int o = 16; o; o >>= 1) sum += __shfl_down_sync(0xffffffffu, sum, o);
    if ((t & 31) == 0) swsum[t >> 5] = sum;
    __syncthreads();
    if (t == 0) {
        float tot = 0.f;
        #pragma unroll
        for (int w = 0; w < 8; w++) tot += swsum[w];
        out[0] = tot;
        g_counter = 0;   // normal-path reset for next graph replay
    }
}

extern "C" void kernel_launch(void* const* d_in, const int* in_sizes, int n_in,
                              void* d_out, int out_size) {
    const float* x = (const float*)d_in[0];
    float* out = (float*)d_out;

    k_centroid_intra<<<S, 128>>>(x);
    k_inter<<<dim3(8, 32), 256>>>(out);
}